// round 4
// baseline (speedup 1.0000x reference)
#include <cuda_runtime.h>
#include <cstdint>

// Problem constants (fixed shapes)
#define NMAX 50000
#define EMAX 800000
#define FDIM 128      // H*C
#define HEADS4 4
#define CPH 32

// ---------------- scratch (device globals; no allocation allowed) ----------
__device__ float g_lin [NMAX * FDIM];   // GEMM output (pre-aggregation h)
__device__ float g_feat[NMAX * FDIM];   // activated features / layer IO
__device__ float g_als [NMAX * HEADS4]; // per-node src logits
__device__ float g_ald [NMAX * HEADS4]; // per-node dst logits
__device__ int   g_counts[NMAX];
__device__ int   g_indptr[NMAX + 1];
__device__ int   g_cursor[NMAX];
__device__ int   g_csr   [EMAX];        // src node per CSR-slot (grouped by dst)
__device__ int   g_is64;

static inline int cdiv(int a, int b) { return (a + b - 1) / b; }

// ---------------- dtype probe: int64 vs int32 edge_index -------------------
// Values are in [0, 50000): if stored as int64, every odd 32-bit word is 0.
__global__ void detect_dtype_kernel(const unsigned int* __restrict__ w) {
    __shared__ int any;
    if (threadIdx.x == 0) any = 0;
    __syncthreads();
    int acc = 0;
    for (int i = threadIdx.x; i < 2048; i += blockDim.x) acc |= (int)w[2 * i + 1];
    atomicOr(&any, acc);
    __syncthreads();
    if (threadIdx.x == 0) g_is64 = (any == 0) ? 1 : 0;
}

// ---------------- CSR build -----------------------------------------------
__global__ void zero_counts_kernel(int n) {
    int i = blockIdx.x * blockDim.x + threadIdx.x;
    if (i < n) g_counts[i] = 0;
}

__global__ void count_dst_kernel(const void* __restrict__ ei, int E) {
    int i = blockIdx.x * blockDim.x + threadIdx.x;
    if (i >= E) return;
    int d = g_is64 ? (int)((const long long*)ei)[(size_t)E + i]
                   : ((const int*)ei)[E + i];
    atomicAdd(&g_counts[d], 1);
}

__global__ void scan_kernel(int n) {
    __shared__ int sh[1024];
    __shared__ int s_off;
    if (threadIdx.x == 0) s_off = 0;
    __syncthreads();
    for (int base = 0; base < n; base += 1024) {
        int i = base + threadIdx.x;
        int v = (i < n) ? g_counts[i] : 0;
        sh[threadIdx.x] = v;
        __syncthreads();
        for (int d = 1; d < 1024; d <<= 1) {
            int t = (threadIdx.x >= (unsigned)d) ? sh[threadIdx.x - d] : 0;
            __syncthreads();
            sh[threadIdx.x] += t;
            __syncthreads();
        }
        int incl = sh[threadIdx.x];
        int off = s_off;
        if (i < n) {
            g_indptr[i] = off + incl - v;
            g_cursor[i] = off + incl - v;
        }
        __syncthreads();
        if (threadIdx.x == 1023) s_off = off + incl;
        __syncthreads();
    }
    if (threadIdx.x == 0) g_indptr[n] = s_off;
}

__global__ void scatter_kernel(const void* __restrict__ ei, int E) {
    int i = blockIdx.x * blockDim.x + threadIdx.x;
    if (i >= E) return;
    int s, d;
    if (g_is64) {
        s = (int)((const long long*)ei)[i];
        d = (int)((const long long*)ei)[(size_t)E + i];
    } else {
        s = ((const int*)ei)[i];
        d = ((const int*)ei)[E + i];
    }
    int pos = atomicAdd(&g_cursor[d], 1);
    g_csr[pos] = s;
}

// ---------------- GEMM: C[M x BN] = A[M x K] @ B[K x BN] -------------------
// BN == actual N == ldb. Register-tiled, fp32. TM fixed to 4 (float4 A reads).
template <int BM, int BN, int TM, int TN>
__global__ void __launch_bounds__(256) gemm_kernel(
    const float* __restrict__ A, const float* __restrict__ B,
    float* __restrict__ C, int M, int K)
{
    constexpr int BK = 16;
    constexpr int TX = BN / TN;
    constexpr int TY = BM / TM;
    static_assert(TX * TY == 256, "256 threads");
    static_assert(TM == 4, "float4 A fragment");
    constexpr int NG = TN / 4;             // float4 groups per thread in N
    constexpr int GS = BN / NG;            // group stride in columns
    constexpr int APAD = 4;

    __shared__ float As[BK][BM + APAD];
    __shared__ float Bs[BK][BN];

    int tid = threadIdx.x;
    int tx = tid % TX, ty = tid / TX;
    int m0 = blockIdx.x * BM;

    float acc[TM][TN];
#pragma unroll
    for (int i = 0; i < TM; i++)
#pragma unroll
        for (int j = 0; j < TN; j++) acc[i][j] = 0.f;

    for (int k0 = 0; k0 < K; k0 += BK) {
        constexpr int AE = BM * BK / 256;
#pragma unroll
        for (int i = 0; i < AE; i++) {
            int idx = tid + i * 256;
            int am = idx / BK, ak = idx % BK;
            int gm = m0 + am;
            As[ak][am] = (gm < M) ? A[(size_t)gm * K + k0 + ak] : 0.f;
        }
        constexpr int BE = BK * BN / 256;
#pragma unroll
        for (int i = 0; i < BE; i++) {
            int idx = tid + i * 256;
            int bk = idx / BN, bn = idx % BN;
            Bs[bk][bn] = B[(size_t)(k0 + bk) * BN + bn];
        }
        __syncthreads();
#pragma unroll
        for (int k = 0; k < BK; k++) {
            float4 av = *(const float4*)&As[k][ty * TM];
            float a[TM] = {av.x, av.y, av.z, av.w};
            float b[TN];
#pragma unroll
            for (int g = 0; g < NG; g++) {
                float4 bv = *(const float4*)&Bs[k][g * GS + tx * 4];
                b[g * 4 + 0] = bv.x; b[g * 4 + 1] = bv.y;
                b[g * 4 + 2] = bv.z; b[g * 4 + 3] = bv.w;
            }
#pragma unroll
            for (int i = 0; i < TM; i++)
#pragma unroll
                for (int j = 0; j < TN; j++) acc[i][j] += a[i] * b[j];
        }
        __syncthreads();
    }
#pragma unroll
    for (int i = 0; i < TM; i++) {
        int gm = m0 + ty * TM + i;
        if (gm >= M) continue;
#pragma unroll
        for (int g = 0; g < NG; g++) {
            float4 v = make_float4(acc[i][g * 4 + 0], acc[i][g * 4 + 1],
                                   acc[i][g * 4 + 2], acc[i][g * 4 + 3]);
            *(float4*)&C[(size_t)gm * BN + g * GS + tx * 4] = v;
        }
    }
}

// ---------------- attention logits: al[n][h] = <h[n,h,:], a[h,:]> ----------
template <int HEADS, int CH>
__global__ void logits_kernel(const float* __restrict__ h,
                              const float* __restrict__ a_src,
                              const float* __restrict__ a_dst, int n)
{
    int idx = blockIdx.x * blockDim.x + threadIdx.x;
    if (idx >= n * HEADS) return;
    int node = idx / HEADS, hd = idx % HEADS;
    const float4* hp  = (const float4*)(h + (size_t)node * HEADS * CH + hd * CH);
    const float4* as4 = (const float4*)(a_src + hd * CH);
    const float4* ad4 = (const float4*)(a_dst + hd * CH);
    float s1 = 0.f, s2 = 0.f;
#pragma unroll
    for (int i = 0; i < CH / 4; i++) {
        float4 hv = hp[i], av = as4[i], dv = ad4[i];
        s1 += hv.x * av.x + hv.y * av.y + hv.z * av.z + hv.w * av.w;
        s2 += hv.x * dv.x + hv.y * dv.y + hv.z * dv.z + hv.w * dv.w;
    }
    g_als[idx] = s1;
    g_ald[idx] = s2;
}

// ---------------- GAT aggregation: one warp per destination node -----------
// 3 passes: max, sum-exp, weighted aggregate. Self-loop handled analytically.
template <int HEADS, int CH, bool ACT>
__global__ void __launch_bounds__(256) gat_agg_kernel(
    const float* __restrict__ h, const float* __restrict__ bias,
    float* __restrict__ out, int n)
{
    constexpr int F = HEADS * CH;
    constexpr int CL = F / 32;                 // channels per lane
    int warp = (blockIdx.x * blockDim.x + threadIdx.x) >> 5;
    int lane = threadIdx.x & 31;
    if (warp >= n) return;

    int start = g_indptr[warp], end = g_indptr[warp + 1];

    float aldv[HEADS], self_e[HEADS], m[HEADS];
    if constexpr (HEADS == 4) {
        float4 t = *(const float4*)&g_ald[warp * 4];
        aldv[0] = t.x; aldv[1] = t.y; aldv[2] = t.z; aldv[3] = t.w;
        float4 u = *(const float4*)&g_als[warp * 4];
        float sv[4] = {u.x, u.y, u.z, u.w};
#pragma unroll
        for (int hh = 0; hh < 4; hh++) {
            float e = sv[hh] + aldv[hh];
            e = e > 0.f ? e : 0.2f * e;
            self_e[hh] = e; m[hh] = e;
        }
    } else {
        aldv[0] = g_ald[warp];
        float e = g_als[warp] + aldv[0];
        e = e > 0.f ? e : 0.2f * e;
        self_e[0] = e; m[0] = e;
    }

    // pass A: max
    for (int eb = start; eb < end; eb += 32) {
        int e = eb + lane;
        if (e < end) {
            int s = g_csr[e];
            if constexpr (HEADS == 4) {
                float4 u = *(const float4*)&g_als[s * 4];
                float sv[4] = {u.x, u.y, u.z, u.w};
#pragma unroll
                for (int hh = 0; hh < 4; hh++) {
                    float x = sv[hh] + aldv[hh];
                    x = x > 0.f ? x : 0.2f * x;
                    m[hh] = fmaxf(m[hh], x);
                }
            } else {
                float x = g_als[s] + aldv[0];
                x = x > 0.f ? x : 0.2f * x;
                m[0] = fmaxf(m[0], x);
            }
        }
    }
#pragma unroll
    for (int hh = 0; hh < HEADS; hh++)
#pragma unroll
        for (int off = 16; off; off >>= 1)
            m[hh] = fmaxf(m[hh], __shfl_xor_sync(0xffffffffu, m[hh], off));

    // pass B: denom
    float den[HEADS];
#pragma unroll
    for (int hh = 0; hh < HEADS; hh++) den[hh] = 0.f;
    for (int eb = start; eb < end; eb += 32) {
        int e = eb + lane;
        if (e < end) {
            int s = g_csr[e];
            if constexpr (HEADS == 4) {
                float4 u = *(const float4*)&g_als[s * 4];
                float sv[4] = {u.x, u.y, u.z, u.w};
#pragma unroll
                for (int hh = 0; hh < 4; hh++) {
                    float x = sv[hh] + aldv[hh];
                    x = x > 0.f ? x : 0.2f * x;
                    den[hh] += __expf(x - m[hh]);
                }
            } else {
                float x = g_als[s] + aldv[0];
                x = x > 0.f ? x : 0.2f * x;
                den[0] += __expf(x - m[0]);
            }
        }
    }
#pragma unroll
    for (int hh = 0; hh < HEADS; hh++) {
#pragma unroll
        for (int off = 16; off; off >>= 1)
            den[hh] += __shfl_xor_sync(0xffffffffu, den[hh], off);
        den[hh] += __expf(self_e[hh] - m[hh]);
        den[hh] = 1.f / (den[hh] + 1e-16f);
    }

    // pass C: aggregate. Lane owns channels [lane*CL, lane*CL+CL), all in one head.
    int myhead = (HEADS == 1) ? 0 : (lane >> 3);
    float mym = m[myhead], myden = den[myhead], mya = aldv[myhead];
    float acc[CL];
    {
        float alpha = __expf(self_e[myhead] - mym) * myden;
        if constexpr (CL == 4) {
            float4 hv = *(const float4*)&h[(size_t)warp * F + lane * 4];
            acc[0] = hv.x * alpha; acc[1] = hv.y * alpha;
            acc[2] = hv.z * alpha; acc[3] = hv.w * alpha;
        } else {
            acc[0] = h[(size_t)warp * F + lane] * alpha;
        }
    }
    int s = (start < end) ? g_csr[start] : 0;   // prefetch pipeline
    for (int e = start; e < end; e++) {
        int snext = (e + 1 < end) ? g_csr[e + 1] : 0;
        float x = g_als[s * HEADS + myhead] + mya;
        x = x > 0.f ? x : 0.2f * x;
        float alpha = __expf(x - mym) * myden;
        if constexpr (CL == 4) {
            float4 hv = *(const float4*)&h[(size_t)s * F + lane * 4];
            acc[0] += hv.x * alpha; acc[1] += hv.y * alpha;
            acc[2] += hv.z * alpha; acc[3] += hv.w * alpha;
        } else {
            acc[0] += h[(size_t)s * F + lane] * alpha;
        }
        s = snext;
    }

#pragma unroll
    for (int j = 0; j < CL; j++) {
        int c = lane * CL + j;
        float v = acc[j] + bias[c];
        if (ACT) v = v > 0.f ? v : (__expf(v) - 1.f);
        out[(size_t)warp * F + c] = v;
    }
}

// ---------------- classifier head + link embedding writeback ---------------
__global__ void head_kernel(const float* __restrict__ h3,
                            const float* __restrict__ Wc,
                            const float* __restrict__ bc,
                            float* __restrict__ out, int n)
{
    int node = blockIdx.x * blockDim.x + threadIdx.x;
    if (node >= n) return;
    float o0 = bc[0], o1 = bc[1];
    float* emb = out + (size_t)n * 2 + (size_t)node * 32;
#pragma unroll
    for (int i = 0; i < 8; i++) {
        float4 v = *(const float4*)&h3[(size_t)node * 32 + i * 4];
        o0 += v.x * Wc[(i * 4 + 0) * 2] + v.y * Wc[(i * 4 + 1) * 2]
            + v.z * Wc[(i * 4 + 2) * 2] + v.w * Wc[(i * 4 + 3) * 2];
        o1 += v.x * Wc[(i * 4 + 0) * 2 + 1] + v.y * Wc[(i * 4 + 1) * 2 + 1]
            + v.z * Wc[(i * 4 + 2) * 2 + 1] + v.w * Wc[(i * 4 + 3) * 2 + 1];
        *(float4*)&emb[i * 4] = v;
    }
    out[(size_t)node * 2 + 0] = o0;
    out[(size_t)node * 2 + 1] = o1;
}

// ---------------- launch ----------------------------------------------------
extern "C" void kernel_launch(void* const* d_in, const int* in_sizes, int n_in,
                              void* d_out, int out_size)
{
    const float*  x    = (const float*)d_in[0];
    const void*   ei   = d_in[1];
    const float*  W1   = (const float*)d_in[2];
    const float*  a1s  = (const float*)d_in[3];
    const float*  a1d  = (const float*)d_in[4];
    const float*  b1   = (const float*)d_in[5];
    const float*  W2   = (const float*)d_in[6];
    const float*  a2s  = (const float*)d_in[7];
    const float*  a2d  = (const float*)d_in[8];
    const float*  b2   = (const float*)d_in[9];
    const float*  W3   = (const float*)d_in[10];
    const float*  a3s  = (const float*)d_in[11];
    const float*  a3d  = (const float*)d_in[12];
    const float*  b3   = (const float*)d_in[13];
    const float*  Wc   = (const float*)d_in[14];
    const float*  bc   = (const float*)d_in[15];
    float* out = (float*)d_out;

    int N = in_sizes[0] / FDIM;     // 50000
    int E = in_sizes[1] / 2;        // 800000 (element count same for i32/i64)

    float *lin, *feat;
    cudaGetSymbolAddress((void**)&lin,  g_lin);
    cudaGetSymbolAddress((void**)&feat, g_feat);

    // --- CSR by destination (rebuilt every replay; deterministic work) ---
    detect_dtype_kernel<<<1, 256>>>((const unsigned int*)ei);
    zero_counts_kernel<<<cdiv(N, 256), 256>>>(N);
    count_dst_kernel<<<cdiv(E, 256), 256>>>(ei, E);
    scan_kernel<<<1, 1024>>>(N);
    scatter_kernel<<<cdiv(E, 256), 256>>>(ei, E);

    // --- layer 1: x[128] -> 128, 4 heads, ELU ---
    gemm_kernel<64, 128, 4, 8><<<cdiv(N, 64), 256>>>(x, W1, lin, N, 128);
    logits_kernel<4, 32><<<cdiv(N * 4, 256), 256>>>(lin, a1s, a1d, N);
    gat_agg_kernel<4, 32, true><<<cdiv(N * 32, 256), 256>>>(lin, b1, feat, N);

    // --- layer 2: 128 -> 128, 4 heads, ELU ---
    gemm_kernel<64, 128, 4, 8><<<cdiv(N, 64), 256>>>(feat, W2, lin, N, 128);
    logits_kernel<4, 32><<<cdiv(N * 4, 256), 256>>>(lin, a2s, a2d, N);
    gat_agg_kernel<4, 32, true><<<cdiv(N * 32, 256), 256>>>(lin, b2, feat, N);

    // --- layer 3: 128 -> 32, 1 head, no activation ---
    gemm_kernel<128, 32, 4, 4><<<cdiv(N, 128), 256>>>(feat, W3, lin, N, 128);
    logits_kernel<1, 32><<<cdiv(N, 256), 256>>>(lin, a3s, a3d, N);
    gat_agg_kernel<1, 32, false><<<cdiv(N * 32, 256), 256>>>(lin, b3, feat, N);

    // --- classifier head + link embedding ---
    head_kernel<<<cdiv(N, 256), 256>>>(feat, Wc, bc, out, N);
}

// round 7
// speedup vs baseline: 1.1481x; 1.1481x over previous
#include <cuda_runtime.h>
#include <cstdint>

// Problem constants (fixed shapes)
#define NMAX 50000
#define EMAX 800000
#define FDIM 128      // H*C
#define HEADS4 4
#define CPH 32

// ---------------- scratch (device globals; no allocation allowed) ----------
__device__ float g_lin [NMAX * FDIM];   // GEMM output (pre-aggregation h)
__device__ float g_feat[NMAX * FDIM];   // activated features / layer IO
__device__ float g_als [NMAX * HEADS4]; // per-node src logits
__device__ float g_ald [NMAX * HEADS4]; // per-node dst logits
__device__ int   g_counts[NMAX];
__device__ int   g_indptr[NMAX + 1];
__device__ int   g_cursor[NMAX];
__device__ int   g_csr   [EMAX];        // src node per CSR-slot (grouped by dst)
__device__ int   g_scanbuf[NMAX];       // per-block exclusive scan
__device__ int   g_blocksum[64];        // block totals -> block offsets
__device__ int   g_is64;

static inline int cdiv(int a, int b) { return (a + b - 1) / b; }

// ---------------- dtype probe: int64 vs int32 edge_index -------------------
// Values are in [0, 50000): if stored as int64, every odd 32-bit word is 0.
__global__ void detect_dtype_kernel(const unsigned int* __restrict__ w) {
    __shared__ int any;
    if (threadIdx.x == 0) any = 0;
    __syncthreads();
    int acc = 0;
    for (int i = threadIdx.x; i < 2048; i += blockDim.x) acc |= (int)w[2 * i + 1];
    atomicOr(&any, acc);
    __syncthreads();
    if (threadIdx.x == 0) g_is64 = (any == 0) ? 1 : 0;
}

// ---------------- CSR build -----------------------------------------------
__global__ void zero_counts_kernel(int n) {
    int i = blockIdx.x * blockDim.x + threadIdx.x;
    if (i < n) g_counts[i] = 0;
}

__global__ void count_dst_kernel(const void* __restrict__ ei, int E) {
    int i = blockIdx.x * blockDim.x + threadIdx.x;
    if (i >= E) return;
    int d = g_is64 ? (int)((const long long*)ei)[(size_t)E + i]
                   : ((const int*)ei)[E + i];
    atomicAdd(&g_counts[d], 1);
}

// --- multi-block scan, stage 1: per-block (1024 elems) exclusive scan ------
__global__ void __launch_bounds__(1024) scan1_kernel(int n) {
    __shared__ int warpsum[32];
    int i = blockIdx.x * 1024 + threadIdx.x;
    int lane = threadIdx.x & 31, w = threadIdx.x >> 5;
    int v = (i < n) ? g_counts[i] : 0;
    int x = v;
#pragma unroll
    for (int d = 1; d < 32; d <<= 1) {
        int t = __shfl_up_sync(0xffffffffu, x, d);
        if (lane >= d) x += t;
    }
    if (lane == 31) warpsum[w] = x;
    __syncthreads();
    if (w == 0) {
        int s = warpsum[lane];
#pragma unroll
        for (int d = 1; d < 32; d <<= 1) {
            int t = __shfl_up_sync(0xffffffffu, s, d);
            if (lane >= d) s += t;
        }
        warpsum[lane] = s;
    }
    __syncthreads();
    int incl = x + (w > 0 ? warpsum[w - 1] : 0);
    if (i < n) g_scanbuf[i] = incl - v;                 // exclusive within block
    if (threadIdx.x == 1023) g_blocksum[blockIdx.x] = incl;
}

// --- stage 2: scan the (<=64) block sums; also writes total -> indptr[n] ---
__global__ void scan2_kernel(int nb, int n) {
    __shared__ int sh[64];
    int t = threadIdx.x;
    int v = (t < nb) ? g_blocksum[t] : 0;
    sh[t] = v;
    __syncthreads();
#pragma unroll
    for (int d = 1; d < 64; d <<= 1) {
        int x = (t >= d) ? sh[t - d] : 0;
        __syncthreads();
        sh[t] += x;
        __syncthreads();
    }
    if (t < nb) g_blocksum[t] = sh[t] - v;              // exclusive block offset
    if (t == 63) g_indptr[n] = sh[63];
}

// --- stage 3: combine -> indptr / cursor -----------------------------------
__global__ void scan3_kernel(int n) {
    int i = blockIdx.x * blockDim.x + threadIdx.x;
    if (i >= n) return;
    int off = g_blocksum[i >> 10] + g_scanbuf[i];
    g_indptr[i] = off;
    g_cursor[i] = off;
}

__global__ void scatter_kernel(const void* __restrict__ ei, int E) {
    int i = blockIdx.x * blockDim.x + threadIdx.x;
    if (i >= E) return;
    int s, d;
    if (g_is64) {
        s = (int)((const long long*)ei)[i];
        d = (int)((const long long*)ei)[(size_t)E + i];
    } else {
        s = ((const int*)ei)[i];
        d = ((const int*)ei)[E + i];
    }
    int pos = atomicAdd(&g_cursor[d], 1);
    g_csr[pos] = s;
}

// ---------------- GEMM: C[M x BN] = A[M x K] @ B[K x BN] -------------------
// BN == actual N == ldb. Register-tiled, fp32. TM in {4,8} (float4 A reads).
template <int BM, int BN, int TM, int TN>
__global__ void __launch_bounds__(256) gemm_kernel(
    const float* __restrict__ A, const float* __restrict__ B,
    float* __restrict__ C, int M, int K)
{
    constexpr int BK = 16;
    constexpr int TX = BN / TN;
    constexpr int TY = BM / TM;
    static_assert(TX * TY == 256, "256 threads");
    static_assert(TM % 4 == 0 && TN % 4 == 0, "float4 fragments");
    constexpr int AG = TM / 4;             // float4 groups per thread in M
    constexpr int NG = TN / 4;             // float4 groups per thread in N
    constexpr int GS = BN / NG;            // group stride in columns
    constexpr int APAD = 4;

    __shared__ float As[BK][BM + APAD];
    __shared__ float Bs[BK][BN];

    int tid = threadIdx.x;
    int tx = tid % TX, ty = tid / TX;
    int m0 = blockIdx.x * BM;

    float acc[TM][TN];
#pragma unroll
    for (int i = 0; i < TM; i++)
#pragma unroll
        for (int j = 0; j < TN; j++) acc[i][j] = 0.f;

    for (int k0 = 0; k0 < K; k0 += BK) {
        constexpr int AE = BM * BK / 256;
#pragma unroll
        for (int i = 0; i < AE; i++) {
            int idx = tid + i * 256;
            int am = idx / BK, ak = idx % BK;
            int gm = m0 + am;
            As[ak][am] = (gm < M) ? A[(size_t)gm * K + k0 + ak] : 0.f;
        }
        constexpr int BE = BK * BN / 256;
#pragma unroll
        for (int i = 0; i < BE; i++) {
            int idx = tid + i * 256;
            int bk = idx / BN, bn = idx % BN;
            Bs[bk][bn] = B[(size_t)(k0 + bk) * BN + bn];
        }
        __syncthreads();
#pragma unroll
        for (int k = 0; k < BK; k++) {
            float a[TM];
#pragma unroll
            for (int g = 0; g < AG; g++) {
                float4 av = *(const float4*)&As[k][ty * TM + g * 4];
                a[g * 4 + 0] = av.x; a[g * 4 + 1] = av.y;
                a[g * 4 + 2] = av.z; a[g * 4 + 3] = av.w;
            }
            float b[TN];
#pragma unroll
            for (int g = 0; g < NG; g++) {
                float4 bv = *(const float4*)&Bs[k][g * GS + tx * 4];
                b[g * 4 + 0] = bv.x; b[g * 4 + 1] = bv.y;
                b[g * 4 + 2] = bv.z; b[g * 4 + 3] = bv.w;
            }
#pragma unroll
            for (int i = 0; i < TM; i++)
#pragma unroll
                for (int j = 0; j < TN; j++) acc[i][j] += a[i] * b[j];
        }
        __syncthreads();
    }
#pragma unroll
    for (int i = 0; i < TM; i++) {
        int gm = m0 + ty * TM + i;
        if (gm >= M) continue;
#pragma unroll
        for (int g = 0; g < NG; g++) {
            float4 v = make_float4(acc[i][g * 4 + 0], acc[i][g * 4 + 1],
                                   acc[i][g * 4 + 2], acc[i][g * 4 + 3]);
            *(float4*)&C[(size_t)gm * BN + g * GS + tx * 4] = v;
        }
    }
}

// ---------------- attention logits: al[n][h] = <h[n,h,:], a[h,:]> ----------
template <int HEADS, int CH>
__global__ void logits_kernel(const float* __restrict__ h,
                              const float* __restrict__ a_src,
                              const float* __restrict__ a_dst, int n)
{
    int idx = blockIdx.x * blockDim.x + threadIdx.x;
    if (idx >= n * HEADS) return;
    int node = idx / HEADS, hd = idx % HEADS;
    const float4* hp  = (const float4*)(h + (size_t)node * HEADS * CH + hd * CH);
    const float4* as4 = (const float4*)(a_src + hd * CH);
    const float4* ad4 = (const float4*)(a_dst + hd * CH);
    float s1 = 0.f, s2 = 0.f;
#pragma unroll
    for (int i = 0; i < CH / 4; i++) {
        float4 hv = hp[i], av = as4[i], dv = ad4[i];
        s1 += hv.x * av.x + hv.y * av.y + hv.z * av.z + hv.w * av.w;
        s2 += hv.x * dv.x + hv.y * dv.y + hv.z * dv.z + hv.w * dv.w;
    }
    g_als[idx] = s1;
    g_ald[idx] = s2;
}

// ---------------- GAT aggregation: one warp per destination node -----------
// 3 passes: max, sum-exp, weighted aggregate. Self-loop handled analytically.
template <int HEADS, int CH, bool ACT>
__global__ void __launch_bounds__(256) gat_agg_kernel(
    const float* __restrict__ h, const float* __restrict__ bias,
    float* __restrict__ out, int n)
{
    constexpr int F = HEADS * CH;
    constexpr int CL = F / 32;                 // channels per lane
    int warp = (blockIdx.x * blockDim.x + threadIdx.x) >> 5;
    int lane = threadIdx.x & 31;
    if (warp >= n) return;

    int start = g_indptr[warp], end = g_indptr[warp + 1];

    float aldv[HEADS], self_e[HEADS], m[HEADS];
    if constexpr (HEADS == 4) {
        float4 t = *(const float4*)&g_ald[warp * 4];
        aldv[0] = t.x; aldv[1] = t.y; aldv[2] = t.z; aldv[3] = t.w;
        float4 u = *(const float4*)&g_als[warp * 4];
        float sv[4] = {u.x, u.y, u.z, u.w};
#pragma unroll
        for (int hh = 0; hh < 4; hh++) {
            float e = sv[hh] + aldv[hh];
            e = e > 0.f ? e : 0.2f * e;
            self_e[hh] = e; m[hh] = e;
        }
    } else {
        aldv[0] = g_ald[warp];
        float e = g_als[warp] + aldv[0];
        e = e > 0.f ? e : 0.2f * e;
        self_e[0] = e; m[0] = e;
    }

    // pass A: max
    for (int eb = start; eb < end; eb += 32) {
        int e = eb + lane;
        if (e < end) {
            int s = g_csr[e];
            if constexpr (HEADS == 4) {
                float4 u = *(const float4*)&g_als[s * 4];
                float sv[4] = {u.x, u.y, u.z, u.w};
#pragma unroll
                for (int hh = 0; hh < 4; hh++) {
                    float x = sv[hh] + aldv[hh];
                    x = x > 0.f ? x : 0.2f * x;
                    m[hh] = fmaxf(m[hh], x);
                }
            } else {
                float x = g_als[s] + aldv[0];
                x = x > 0.f ? x : 0.2f * x;
                m[0] = fmaxf(m[0], x);
            }
        }
    }
#pragma unroll
    for (int hh = 0; hh < HEADS; hh++)
#pragma unroll
        for (int off = 16; off; off >>= 1)
            m[hh] = fmaxf(m[hh], __shfl_xor_sync(0xffffffffu, m[hh], off));

    // pass B: denom
    float den[HEADS];
#pragma unroll
    for (int hh = 0; hh < HEADS; hh++) den[hh] = 0.f;
    for (int eb = start; eb < end; eb += 32) {
        int e = eb + lane;
        if (e < end) {
            int s = g_csr[e];
            if constexpr (HEADS == 4) {
                float4 u = *(const float4*)&g_als[s * 4];
                float sv[4] = {u.x, u.y, u.z, u.w};
#pragma unroll
                for (int hh = 0; hh < 4; hh++) {
                    float x = sv[hh] + aldv[hh];
                    x = x > 0.f ? x : 0.2f * x;
                    den[hh] += __expf(x - m[hh]);
                }
            } else {
                float x = g_als[s] + aldv[0];
                x = x > 0.f ? x : 0.2f * x;
                den[0] += __expf(x - m[0]);
            }
        }
    }
#pragma unroll
    for (int hh = 0; hh < HEADS; hh++) {
#pragma unroll
        for (int off = 16; off; off >>= 1)
            den[hh] += __shfl_xor_sync(0xffffffffu, den[hh], off);
        den[hh] += __expf(self_e[hh] - m[hh]);
        den[hh] = 1.f / (den[hh] + 1e-16f);
    }

    // pass C: aggregate. Lane owns channels [lane*CL, lane*CL+CL), all in one head.
    int myhead = (HEADS == 1) ? 0 : (lane >> 3);
    float mym = m[myhead], myden = den[myhead], mya = aldv[myhead];
    float acc[CL];
    {
        float alpha = __expf(self_e[myhead] - mym) * myden;
        if constexpr (CL == 4) {
            float4 hv = *(const float4*)&h[(size_t)warp * F + lane * 4];
            acc[0] = hv.x * alpha; acc[1] = hv.y * alpha;
            acc[2] = hv.z * alpha; acc[3] = hv.w * alpha;
        } else {
            acc[0] = h[(size_t)warp * F + lane] * alpha;
        }
    }
    int s = (start < end) ? g_csr[start] : 0;   // prefetch pipeline
    for (int e = start; e < end; e++) {
        int snext = (e + 1 < end) ? g_csr[e + 1] : 0;
        float x = g_als[s * HEADS + myhead] + mya;
        x = x > 0.f ? x : 0.2f * x;
        float alpha = __expf(x - mym) * myden;
        if constexpr (CL == 4) {
            float4 hv = *(const float4*)&h[(size_t)s * F + lane * 4];
            acc[0] += hv.x * alpha; acc[1] += hv.y * alpha;
            acc[2] += hv.z * alpha; acc[3] += hv.w * alpha;
        } else {
            acc[0] += h[(size_t)s * F + lane] * alpha;
        }
        s = snext;
    }

#pragma unroll
    for (int j = 0; j < CL; j++) {
        int c = lane * CL + j;
        float v = acc[j] + bias[c];
        if (ACT) v = v > 0.f ? v : (__expf(v) - 1.f);
        out[(size_t)warp * F + c] = v;
    }
}

// ---------------- classifier head + link embedding writeback ---------------
__global__ void head_kernel(const float* __restrict__ h3,
                            const float* __restrict__ Wc,
                            const float* __restrict__ bc,
                            float* __restrict__ out, int n)
{
    int node = blockIdx.x * blockDim.x + threadIdx.x;
    if (node >= n) return;
    float o0 = bc[0], o1 = bc[1];
    float* emb = out + (size_t)n * 2 + (size_t)node * 32;
#pragma unroll
    for (int i = 0; i < 8; i++) {
        float4 v = *(const float4*)&h3[(size_t)node * 32 + i * 4];
        o0 += v.x * Wc[(i * 4 + 0) * 2] + v.y * Wc[(i * 4 + 1) * 2]
            + v.z * Wc[(i * 4 + 2) * 2] + v.w * Wc[(i * 4 + 3) * 2];
        o1 += v.x * Wc[(i * 4 + 0) * 2 + 1] + v.y * Wc[(i * 4 + 1) * 2 + 1]
            + v.z * Wc[(i * 4 + 2) * 2 + 1] + v.w * Wc[(i * 4 + 3) * 2 + 1];
        *(float4*)&emb[i * 4] = v;
    }
    out[(size_t)node * 2 + 0] = o0;
    out[(size_t)node * 2 + 1] = o1;
}

// ---------------- launch ----------------------------------------------------
extern "C" void kernel_launch(void* const* d_in, const int* in_sizes, int n_in,
                              void* d_out, int out_size)
{
    const float*  x    = (const float*)d_in[0];
    const void*   ei   = d_in[1];
    const float*  W1   = (const float*)d_in[2];
    const float*  a1s  = (const float*)d_in[3];
    const float*  a1d  = (const float*)d_in[4];
    const float*  b1   = (const float*)d_in[5];
    const float*  W2   = (const float*)d_in[6];
    const float*  a2s  = (const float*)d_in[7];
    const float*  a2d  = (const float*)d_in[8];
    const float*  b2   = (const float*)d_in[9];
    const float*  W3   = (const float*)d_in[10];
    const float*  a3s  = (const float*)d_in[11];
    const float*  a3d  = (const float*)d_in[12];
    const float*  b3   = (const float*)d_in[13];
    const float*  Wc   = (const float*)d_in[14];
    const float*  bc   = (const float*)d_in[15];
    float* out = (float*)d_out;

    int N = in_sizes[0] / FDIM;     // 50000
    int E = in_sizes[1] / 2;        // 800000 (element count same for i32/i64)

    float *lin, *feat;
    cudaGetSymbolAddress((void**)&lin,  g_lin);
    cudaGetSymbolAddress((void**)&feat, g_feat);

    // --- CSR by destination (rebuilt every replay; deterministic work) ---
    detect_dtype_kernel<<<1, 256>>>((const unsigned int*)ei);
    zero_counts_kernel<<<cdiv(N, 256), 256>>>(N);
    count_dst_kernel<<<cdiv(E, 256), 256>>>(ei, E);
    int nb = cdiv(N, 1024);
    scan1_kernel<<<nb, 1024>>>(N);
    scan2_kernel<<<1, 64>>>(nb, N);
    scan3_kernel<<<cdiv(N, 256), 256>>>(N);
    scatter_kernel<<<cdiv(E, 256), 256>>>(ei, E);

    // --- layer 1: x[128] -> 128, 4 heads, ELU ---
    gemm_kernel<128, 128, 8, 8><<<cdiv(N, 128), 256>>>(x, W1, lin, N, 128);
    logits_kernel<4, 32><<<cdiv(N * 4, 256), 256>>>(lin, a1s, a1d, N);
    gat_agg_kernel<4, 32, true><<<cdiv(N * 32, 256), 256>>>(lin, b1, feat, N);

    // --- layer 2: 128 -> 128, 4 heads, ELU ---
    gemm_kernel<128, 128, 8, 8><<<cdiv(N, 128), 256>>>(feat, W2, lin, N, 128);
    logits_kernel<4, 32><<<cdiv(N * 4, 256), 256>>>(lin, a2s, a2d, N);
    gat_agg_kernel<4, 32, true><<<cdiv(N * 32, 256), 256>>>(lin, b2, feat, N);

    // --- layer 3: 128 -> 32, 1 head, no activation ---
    gemm_kernel<128, 32, 4, 4><<<cdiv(N, 128), 256>>>(feat, W3, lin, N, 128);
    logits_kernel<1, 32><<<cdiv(N, 256), 256>>>(lin, a3s, a3d, N);
    gat_agg_kernel<1, 32, false><<<cdiv(N * 32, 256), 256>>>(lin, b3, feat, N);

    // --- classifier head + link embedding ---
    head_kernel<<<cdiv(N, 256), 256>>>(feat, Wc, bc, out, N);
}